// round 2
// baseline (speedup 1.0000x reference)
#include <cuda_runtime.h>

// ---------------------------------------------------------------------------
// SCM_MLP: 4 chained layers of  out = relu(out @ (W*mask)^T + exp(mu+sigma*z))
// with per-layer activations concatenated into d_out [B, 4*H].
//
// Strategy (round 1): fp32 SGEMM on CUDA cores using packed fma.rn.f32x2
// (FFMA2: 2x the FFMA rate; ptxas never emits it from C++ so we inline PTX),
// mask pre-multiplied into a __device__ scratch, noise+relu fused in the
// GEMM epilogue, layer chaining through d_out itself (ld = 4*H).
// ---------------------------------------------------------------------------

static constexpr int NL = 4;
static constexpr int NB = 4096;   // batch
static constexpr int NH = 4096;   // hidden
static constexpr int BM = 128;
static constexpr int BN = 128;
static constexpr int BK = 16;
static constexpr int THREADS = 256;

// Masked-weight scratch: 4 * 4096 * 4096 floats = 256 MiB (module-load alloc,
// the sanctioned workaround for no-cudaMalloc).
__device__ float g_wm[(size_t)NL * NH * NH];

// ---------------------------------------------------------------------------
// Prepass: Wm = W * mask, float4-vectorized.
// ---------------------------------------------------------------------------
__global__ void maskmul_kernel(const float* __restrict__ w,
                               const float* __restrict__ m) {
    size_t i = (size_t)blockIdx.x * blockDim.x + threadIdx.x;  // float4 index
    float4 a = ((const float4*)w)[i];
    float4 b = ((const float4*)m)[i];
    float4 r;
    r.x = a.x * b.x; r.y = a.y * b.y; r.z = a.z * b.z; r.w = a.w * b.w;
    ((float4*)g_wm)[i] = r;
}

// ---------------------------------------------------------------------------
// Fused GEMM + lognormal-noise + ReLU.
//   C[b, o] = relu( sum_i A[b,i] * Wm[o,i] + exp(mu[o] + sigma[o]*z[b,o]) )
// A: [M, K] row-major with leading dim lda (x for layer 0, d_out slice after).
// Wm: [N, K] row-major (K contiguous) -> classic NT GEMM.
// C: pre-offset to out + l*H, row stride 4*H.
// ---------------------------------------------------------------------------
__global__ void __launch_bounds__(THREADS, 2)
gemm_fused_kernel(const float* __restrict__ A, int lda, int layer,
                  const float* __restrict__ z,
                  const float* __restrict__ mu,
                  const float* __restrict__ sig,
                  float* __restrict__ C) {
    __shared__ float As[BK][BM];
    __shared__ float Bs[BK][BN];

    const float* Wm = g_wm + (size_t)layer * NH * NH;

    const int t  = threadIdx.x;
    const int m0 = blockIdx.y * BM;
    const int n0 = blockIdx.x * BN;
    const int tx = t & 15;          // 16 col groups
    const int ty = t >> 4;          // 16 row groups
    const int rm = ty * 8;          // this thread's 8 rows within tile
    const int cn = tx * 8;          // this thread's 8 cols within tile

    // Global->smem load decomposition: 512 float4 per 128x16 tile, 2/thread.
    const int r0  = t >> 2;                 // rows 0..63
    const int r1  = r0 + 64;                // rows 64..127
    const int kc  = (t & 3) << 2;           // k-offset within tile (0,4,8,12)

    const float* Ag0 = A  + (size_t)(m0 + r0) * lda + kc;
    const float* Ag1 = A  + (size_t)(m0 + r1) * lda + kc;
    const float* Bg0 = Wm + (size_t)(n0 + r0) * NH  + kc;
    const float* Bg1 = Wm + (size_t)(n0 + r1) * NH  + kc;

    // 8x8 accumulator as 8x4 packed f32x2 pairs (pairs along N).
    unsigned long long acc[8][4];
#pragma unroll
    for (int i = 0; i < 8; i++)
#pragma unroll
        for (int j = 0; j < 4; j++) acc[i][j] = 0ull;

    float4 sA0, sA1, sB0, sB1;

#define SCATTER_TILE()                                                        \
    do {                                                                      \
        As[kc + 0][r0] = sA0.x; As[kc + 1][r0] = sA0.y;                       \
        As[kc + 2][r0] = sA0.z; As[kc + 3][r0] = sA0.w;                       \
        As[kc + 0][r1] = sA1.x; As[kc + 1][r1] = sA1.y;                       \
        As[kc + 2][r1] = sA1.z; As[kc + 3][r1] = sA1.w;                       \
        Bs[kc + 0][r0] = sB0.x; Bs[kc + 1][r0] = sB0.y;                       \
        Bs[kc + 2][r0] = sB0.z; Bs[kc + 3][r0] = sB0.w;                       \
        Bs[kc + 0][r1] = sB1.x; Bs[kc + 1][r1] = sB1.y;                       \
        Bs[kc + 2][r1] = sB1.z; Bs[kc + 3][r1] = sB1.w;                       \
    } while (0)

    // Prologue: tile 0
    sA0 = *(const float4*)(Ag0);
    sA1 = *(const float4*)(Ag1);
    sB0 = *(const float4*)(Bg0);
    sB1 = *(const float4*)(Bg1);
    SCATTER_TILE();
    __syncthreads();

    const int NKT = NH / BK;  // 256 k-tiles
    for (int kt = 0; kt < NKT; kt++) {
        const bool more = (kt + 1 < NKT);
        if (more) {
            const int off = (kt + 1) * BK;  // floats
            sA0 = *(const float4*)(Ag0 + off);
            sA1 = *(const float4*)(Ag1 + off);
            sB0 = *(const float4*)(Bg0 + off);
            sB1 = *(const float4*)(Bg1 + off);
        }

#pragma unroll
        for (int k = 0; k < BK; k++) {
            float4 a0 = *(const float4*)&As[k][rm];
            float4 a1 = *(const float4*)&As[k][rm + 4];
            ulonglong2 q0 = *(const ulonglong2*)&Bs[k][cn];
            ulonglong2 q1 = *(const ulonglong2*)&Bs[k][cn + 4];
            float av[8] = {a0.x, a0.y, a0.z, a0.w, a1.x, a1.y, a1.z, a1.w};
#pragma unroll
            for (int i = 0; i < 8; i++) {
                unsigned long long aa;
                asm("mov.b64 %0, {%1, %1};" : "=l"(aa) : "f"(av[i]));
                asm("fma.rn.f32x2 %0, %1, %2, %0;"
                    : "+l"(acc[i][0]) : "l"(aa), "l"(q0.x));
                asm("fma.rn.f32x2 %0, %1, %2, %0;"
                    : "+l"(acc[i][1]) : "l"(aa), "l"(q0.y));
                asm("fma.rn.f32x2 %0, %1, %2, %0;"
                    : "+l"(acc[i][2]) : "l"(aa), "l"(q1.x));
                asm("fma.rn.f32x2 %0, %1, %2, %0;"
                    : "+l"(acc[i][3]) : "l"(aa), "l"(q1.y));
            }
        }

        if (more) {
            __syncthreads();
            SCATTER_TILE();
            __syncthreads();
        }
    }

    // ---------------- epilogue: noise + relu + store ----------------
    const int go = n0 + cn;
    float4 mu0 = *(const float4*)(mu + go);
    float4 mu1 = *(const float4*)(mu + go + 4);
    float4 sg0 = *(const float4*)(sig + go);
    float4 sg1 = *(const float4*)(sig + go + 4);
    float muv[8] = {mu0.x, mu0.y, mu0.z, mu0.w, mu1.x, mu1.y, mu1.z, mu1.w};
    float sgv[8] = {sg0.x, sg0.y, sg0.z, sg0.w, sg1.x, sg1.y, sg1.z, sg1.w};

#pragma unroll
    for (int i = 0; i < 8; i++) {
        const int gb = m0 + rm + i;
        const float* zr = z + (size_t)gb * NH + go;
        float4 zv0 = *(const float4*)(zr);
        float4 zv1 = *(const float4*)(zr + 4);
        float zz[8] = {zv0.x, zv0.y, zv0.z, zv0.w, zv1.x, zv1.y, zv1.z, zv1.w};

        float res[8];
#pragma unroll
        for (int j = 0; j < 4; j++) {
            float lo, hi;
            asm("mov.b64 {%0, %1}, %2;" : "=f"(lo), "=f"(hi) : "l"(acc[i][j]));
            res[2 * j]     = lo;
            res[2 * j + 1] = hi;
        }
#pragma unroll
        for (int u = 0; u < 8; u++) {
            float noise = __expf(fmaf(sgv[u], zz[u], muv[u]));
            res[u] = fmaxf(res[u] + noise, 0.0f);
        }

        float* cr = C + (size_t)gb * (4 * NH) + go;
        float4 o0; o0.x = res[0]; o0.y = res[1]; o0.z = res[2]; o0.w = res[3];
        float4 o1; o1.x = res[4]; o1.y = res[5]; o1.z = res[6]; o1.w = res[7];
        *(float4*)(cr)     = o0;
        *(float4*)(cr + 4) = o1;
    }
#undef SCATTER_TILE
}

// ---------------------------------------------------------------------------
// kernel_launch: 1 prepass + 4 chained fused GEMMs, all graph-capturable.
// Input order (metadata): x, weights, masks, mu, sigma, z. Output: float32.
// ---------------------------------------------------------------------------
extern "C" void kernel_launch(void* const* d_in, const int* in_sizes, int n_in,
                              void* d_out, int out_size) {
    const float* x   = (const float*)d_in[0];  // [B, H]
    const float* w   = (const float*)d_in[1];  // [L, H, H]
    const float* mk  = (const float*)d_in[2];  // [L, H, H]
    const float* mu  = (const float*)d_in[3];  // [L, H]
    const float* sg  = (const float*)d_in[4];  // [L, H]
    const float* z   = (const float*)d_in[5];  // [L, B, H]
    float*       out = (float*)d_out;          // [B, L*H]

    // Prepass: Wm = W * mask  (L*H*H / 4 float4 elements)
    const size_t n4 = (size_t)NL * NH * NH / 4;
    maskmul_kernel<<<(unsigned)(n4 / THREADS), THREADS>>>(w, mk);

    dim3 grid(NH / BN, NB / BM);  // (32, 32)
    for (int l = 0; l < NL; l++) {
        const float* Ap  = (l == 0) ? x : (out + (size_t)(l - 1) * NH);
        const int    lda = (l == 0) ? NH : 4 * NH;
        gemm_fused_kernel<<<grid, THREADS>>>(
            Ap, lda, l,
            z + (size_t)l * NB * NH,
            mu + (size_t)l * NH,
            sg + (size_t)l * NH,
            out + (size_t)l * NH);
    }
}

// round 3
// speedup vs baseline: 1.0017x; 1.0017x over previous
#include <cuda_runtime.h>

// ---------------------------------------------------------------------------
// SCM_MLP: 4 chained layers of  out = relu(out @ (W*mask)^T + exp(mu+sigma*z))
// with per-layer activations concatenated into d_out [B, 4*H].
//
// Strategy (round 1): fp32 SGEMM on CUDA cores using packed fma.rn.f32x2
// (FFMA2: 2x the FFMA rate; ptxas never emits it from C++ so we inline PTX),
// mask pre-multiplied into a __device__ scratch, noise+relu fused in the
// GEMM epilogue, layer chaining through d_out itself (ld = 4*H).
// ---------------------------------------------------------------------------

static constexpr int NL = 4;
static constexpr int NB = 4096;   // batch
static constexpr int NH = 4096;   // hidden
static constexpr int BM = 128;
static constexpr int BN = 128;
static constexpr int BK = 16;
static constexpr int THREADS = 256;

// Masked-weight scratch: 4 * 4096 * 4096 floats = 256 MiB (module-load alloc,
// the sanctioned workaround for no-cudaMalloc).
__device__ float g_wm[(size_t)NL * NH * NH];

// ---------------------------------------------------------------------------
// Prepass: Wm = W * mask, float4-vectorized.
// ---------------------------------------------------------------------------
__global__ void maskmul_kernel(const float* __restrict__ w,
                               const float* __restrict__ m) {
    size_t i = (size_t)blockIdx.x * blockDim.x + threadIdx.x;  // float4 index
    float4 a = ((const float4*)w)[i];
    float4 b = ((const float4*)m)[i];
    float4 r;
    r.x = a.x * b.x; r.y = a.y * b.y; r.z = a.z * b.z; r.w = a.w * b.w;
    ((float4*)g_wm)[i] = r;
}

// ---------------------------------------------------------------------------
// Fused GEMM + lognormal-noise + ReLU.
//   C[b, o] = relu( sum_i A[b,i] * Wm[o,i] + exp(mu[o] + sigma[o]*z[b,o]) )
// A: [M, K] row-major with leading dim lda (x for layer 0, d_out slice after).
// Wm: [N, K] row-major (K contiguous) -> classic NT GEMM.
// C: pre-offset to out + l*H, row stride 4*H.
// ---------------------------------------------------------------------------
__global__ void __launch_bounds__(THREADS, 2)
gemm_fused_kernel(const float* __restrict__ A, int lda, int layer,
                  const float* __restrict__ z,
                  const float* __restrict__ mu,
                  const float* __restrict__ sig,
                  float* __restrict__ C) {
    __shared__ float As[BK][BM];
    __shared__ float Bs[BK][BN];

    const float* Wm = g_wm + (size_t)layer * NH * NH;

    const int t  = threadIdx.x;
    const int m0 = blockIdx.y * BM;
    const int n0 = blockIdx.x * BN;
    const int tx = t & 15;          // 16 col groups
    const int ty = t >> 4;          // 16 row groups
    const int rm = ty * 8;          // this thread's 8 rows within tile
    const int cn = tx * 8;          // this thread's 8 cols within tile

    // Global->smem load decomposition: 512 float4 per 128x16 tile, 2/thread.
    const int r0  = t >> 2;                 // rows 0..63
    const int r1  = r0 + 64;                // rows 64..127
    const int kc  = (t & 3) << 2;           // k-offset within tile (0,4,8,12)

    const float* Ag0 = A  + (size_t)(m0 + r0) * lda + kc;
    const float* Ag1 = A  + (size_t)(m0 + r1) * lda + kc;
    const float* Bg0 = Wm + (size_t)(n0 + r0) * NH  + kc;
    const float* Bg1 = Wm + (size_t)(n0 + r1) * NH  + kc;

    // 8x8 accumulator as 8x4 packed f32x2 pairs (pairs along N).
    unsigned long long acc[8][4];
#pragma unroll
    for (int i = 0; i < 8; i++)
#pragma unroll
        for (int j = 0; j < 4; j++) acc[i][j] = 0ull;

    float4 sA0, sA1, sB0, sB1;

#define SCATTER_TILE()                                                        \
    do {                                                                      \
        As[kc + 0][r0] = sA0.x; As[kc + 1][r0] = sA0.y;                       \
        As[kc + 2][r0] = sA0.z; As[kc + 3][r0] = sA0.w;                       \
        As[kc + 0][r1] = sA1.x; As[kc + 1][r1] = sA1.y;                       \
        As[kc + 2][r1] = sA1.z; As[kc + 3][r1] = sA1.w;                       \
        Bs[kc + 0][r0] = sB0.x; Bs[kc + 1][r0] = sB0.y;                       \
        Bs[kc + 2][r0] = sB0.z; Bs[kc + 3][r0] = sB0.w;                       \
        Bs[kc + 0][r1] = sB1.x; Bs[kc + 1][r1] = sB1.y;                       \
        Bs[kc + 2][r1] = sB1.z; Bs[kc + 3][r1] = sB1.w;                       \
    } while (0)

    // Prologue: tile 0
    sA0 = *(const float4*)(Ag0);
    sA1 = *(const float4*)(Ag1);
    sB0 = *(const float4*)(Bg0);
    sB1 = *(const float4*)(Bg1);
    SCATTER_TILE();
    __syncthreads();

    const int NKT = NH / BK;  // 256 k-tiles
    for (int kt = 0; kt < NKT; kt++) {
        const bool more = (kt + 1 < NKT);
        if (more) {
            const int off = (kt + 1) * BK;  // floats
            sA0 = *(const float4*)(Ag0 + off);
            sA1 = *(const float4*)(Ag1 + off);
            sB0 = *(const float4*)(Bg0 + off);
            sB1 = *(const float4*)(Bg1 + off);
        }

#pragma unroll
        for (int k = 0; k < BK; k++) {
            float4 a0 = *(const float4*)&As[k][rm];
            float4 a1 = *(const float4*)&As[k][rm + 4];
            ulonglong2 q0 = *(const ulonglong2*)&Bs[k][cn];
            ulonglong2 q1 = *(const ulonglong2*)&Bs[k][cn + 4];
            float av[8] = {a0.x, a0.y, a0.z, a0.w, a1.x, a1.y, a1.z, a1.w};
#pragma unroll
            for (int i = 0; i < 8; i++) {
                unsigned long long aa;
                asm("mov.b64 %0, {%1, %1};" : "=l"(aa) : "f"(av[i]));
                asm("fma.rn.f32x2 %0, %1, %2, %0;"
                    : "+l"(acc[i][0]) : "l"(aa), "l"(q0.x));
                asm("fma.rn.f32x2 %0, %1, %2, %0;"
                    : "+l"(acc[i][1]) : "l"(aa), "l"(q0.y));
                asm("fma.rn.f32x2 %0, %1, %2, %0;"
                    : "+l"(acc[i][2]) : "l"(aa), "l"(q1.x));
                asm("fma.rn.f32x2 %0, %1, %2, %0;"
                    : "+l"(acc[i][3]) : "l"(aa), "l"(q1.y));
            }
        }

        if (more) {
            __syncthreads();
            SCATTER_TILE();
            __syncthreads();
        }
    }

    // ---------------- epilogue: noise + relu + store ----------------
    const int go = n0 + cn;
    float4 mu0 = *(const float4*)(mu + go);
    float4 mu1 = *(const float4*)(mu + go + 4);
    float4 sg0 = *(const float4*)(sig + go);
    float4 sg1 = *(const float4*)(sig + go + 4);
    float muv[8] = {mu0.x, mu0.y, mu0.z, mu0.w, mu1.x, mu1.y, mu1.z, mu1.w};
    float sgv[8] = {sg0.x, sg0.y, sg0.z, sg0.w, sg1.x, sg1.y, sg1.z, sg1.w};

#pragma unroll
    for (int i = 0; i < 8; i++) {
        const int gb = m0 + rm + i;
        const float* zr = z + (size_t)gb * NH + go;
        float4 zv0 = *(const float4*)(zr);
        float4 zv1 = *(const float4*)(zr + 4);
        float zz[8] = {zv0.x, zv0.y, zv0.z, zv0.w, zv1.x, zv1.y, zv1.z, zv1.w};

        float res[8];
#pragma unroll
        for (int j = 0; j < 4; j++) {
            float lo, hi;
            asm("mov.b64 {%0, %1}, %2;" : "=f"(lo), "=f"(hi) : "l"(acc[i][j]));
            res[2 * j]     = lo;
            res[2 * j + 1] = hi;
        }
#pragma unroll
        for (int u = 0; u < 8; u++) {
            float noise = __expf(fmaf(sgv[u], zz[u], muv[u]));
            res[u] = fmaxf(res[u] + noise, 0.0f);
        }

        float* cr = C + (size_t)gb * (4 * NH) + go;
        float4 o0; o0.x = res[0]; o0.y = res[1]; o0.z = res[2]; o0.w = res[3];
        float4 o1; o1.x = res[4]; o1.y = res[5]; o1.z = res[6]; o1.w = res[7];
        *(float4*)(cr)     = o0;
        *(float4*)(cr + 4) = o1;
    }
#undef SCATTER_TILE
}

// ---------------------------------------------------------------------------
// kernel_launch: 1 prepass + 4 chained fused GEMMs, all graph-capturable.
// Input order (metadata): x, weights, masks, mu, sigma, z. Output: float32.
// ---------------------------------------------------------------------------
extern "C" void kernel_launch(void* const* d_in, const int* in_sizes, int n_in,
                              void* d_out, int out_size) {
    const float* x   = (const float*)d_in[0];  // [B, H]
    const float* w   = (const float*)d_in[1];  // [L, H, H]
    const float* mk  = (const float*)d_in[2];  // [L, H, H]
    const float* mu  = (const float*)d_in[3];  // [L, H]
    const float* sg  = (const float*)d_in[4];  // [L, H]
    const float* z   = (const float*)d_in[5];  // [L, B, H]
    float*       out = (float*)d_out;          // [B, L*H]

    // Prepass: Wm = W * mask  (L*H*H / 4 float4 elements)
    const size_t n4 = (size_t)NL * NH * NH / 4;
    maskmul_kernel<<<(unsigned)(n4 / THREADS), THREADS>>>(w, mk);

    dim3 grid(NH / BN, NB / BM);  // (32, 32)
    for (int l = 0; l < NL; l++) {
        const float* Ap  = (l == 0) ? x : (out + (size_t)(l - 1) * NH);
        const int    lda = (l == 0) ? NH : 4 * NH;
        gemm_fused_kernel<<<grid, THREADS>>>(
            Ap, lda, l,
            z + (size_t)l * NB * NH,
            mu + (size_t)l * NH,
            sg + (size_t)l * NH,
            out + (size_t)l * NH);
    }
}